// round 1
// baseline (speedup 1.0000x reference)
#include <cuda_runtime.h>
#include <cstdint>

// Problem constants (fixed by the reference): B=2, N=65536, M=8192, K=32
// TOTAL_GIBS=64 (16 cy, 16 cone, 16 disk, 16 ellip), NUM_OBSERVERS=16
#define EPSV 1e-8f
#define LOG2E_F 1.4426950408889634f

constexpr int Bc = 2;
constexpr int Nc = 65536;
constexpr int Mc = 8192;
constexpr int Kc = 32;
constexpr int NQ = Bc * Mc;          // 16384 queries
constexpr int WARPS_PER_BLOCK = 8;
constexpr int THREADS = WARPS_PER_BLOCK * 32;
constexpr int GRID_BLOCKS = 304;     // ~2 blocks/SM on 152-SM GB300, persistent

__device__ __forceinline__ float ex2f(float x) {
    float r; asm("ex2.approx.ftz.f32 %0, %1;" : "=f"(r) : "f"(x)); return r;
}
__device__ __forceinline__ float sqrtaf(float x) {
    float r; asm("sqrt.approx.ftz.f32 %0, %1;" : "=f"(r) : "f"(x)); return r;
}

__global__ __launch_bounds__(THREADS, 2)
void gib_kernel(const float* __restrict__ points,
                const float* __restrict__ q_coords,
                const int*   __restrict__ support_idxs,
                const float* __restrict__ cy_p,
                const float* __restrict__ cone_p,
                const float* __restrict__ disk_p,
                const float* __restrict__ ellip_p,
                const float* __restrict__ lambdas,
                float* __restrict__ out)
{
    __shared__ float4 sdata[WARPS_PER_BLOCK][32];

    const int lane  = threadIdx.x & 31;
    const int wslot = threadIdx.x >> 5;
    const int gwarp = blockIdx.x * WARPS_PER_BLOCK + wslot;
    const int nwarps = gridDim.x * WARPS_PER_BLOCK;

    // ---- per-lane constants (lane l owns gib g0=l and gib g1=l+32) ----
    // g0: l<16 -> cylinder l  (u = r2,  w = a^2)
    //     l>=16 -> cone l-16  (u = s,   w = b*rz)
    // g1: l<16 -> disk l      (arg = rx2*q1 + ry2*q2 + rz2*q3, q1=q2)
    //     l>=16 -> ellip l-16 (per-axis q1,q2,q3)
    float wa, wb, c0, q1, q2, q3;
    if (lane < 16) {
        float a  = cy_p[lane * 2 + 0];
        float sg = cy_p[lane * 2 + 1];
        wa = a * a; wb = 0.f;
        c0 = -LOG2E_F / (2.f * sg * sg + EPSV);
        float d0 = disk_p[lane * 2 + 0];
        float d1 = disk_p[lane * 2 + 1];
        q1 = -LOG2E_F / (d0 * d0 + EPSV);
        q2 = q1;
        q3 = -LOG2E_F / (d1 * d1 + EPSV);
    } else {
        int j = lane - 16;
        float a  = cone_p[j * 2 + 0];
        float sg = cone_p[j * 2 + 1];
        wa = 0.f; wb = a;
        c0 = -LOG2E_F / (2.f * sg * sg + EPSV);
        float e0 = ellip_p[j * 3 + 0];
        float e1 = ellip_p[j * 3 + 1];
        float e2 = ellip_p[j * 3 + 2];
        q1 = -LOG2E_F / (e0 * e0 + EPSV);
        q2 = -LOG2E_F / (e1 * e1 + EPSV);
        q3 = -LOG2E_F / (e2 * e2 + EPSV);
    }
    const bool useR2 = (lane < 16);

    // lambdas rows for this lane's two gibs, pre-scaled by 1/K (mean fold)
    float L0[16], L1[16];
    const float invK = 1.f / (float)Kc;
    #pragma unroll
    for (int j = 0; j < 16; j++) {
        L0[j] = lambdas[lane * 16 + j] * invK;
        L1[j] = lambdas[(lane + 32) * 16 + j] * invK;
    }

    for (int q = gwarp; q < NQ; q += nwarps) {
        // gather phase: lane k handles support point k
        const float* qc = q_coords + q * 3;
        float qx = __ldg(qc + 0);
        float qy = __ldg(qc + 1);
        float qz = __ldg(qc + 2);
        int   idx = __ldg(support_idxs + q * Kc + lane);
        int   b   = q >> 13;                  // q / Mc
        const float* p = points + (b * Nc + idx) * 3;
        float rx = __ldg(p + 0) - qx;
        float ry = __ldg(p + 1) - qy;
        float rz = __ldg(p + 2) - qz;
        float rx2 = rx * rx;
        float ry2 = ry * ry;
        float s   = sqrtaf(rx2 + ry2 + EPSV);

        sdata[wslot][lane] = make_float4(rx2, ry2, rz, s);
        __syncwarp();

        float acc0 = 0.f, acc1 = 0.f;
        #pragma unroll
        for (int k = 0; k < Kc; k++) {
            float4 v  = sdata[wslot][k];       // broadcast LDS.128
            float r2  = v.x + v.y;
            float rz2 = v.z * v.z;
            float u   = useR2 ? r2 : v.w;
            float w   = fmaf(wb, v.z, wa);
            float d   = u - w;
            acc0 += ex2f(d * c0 * d);
            float a1 = fmaf(rz2, q3, fmaf(v.y, q2, v.x * q1));
            acc1 += ex2f(a1);
        }
        __syncwarp();   // reads done before next iteration's stores

        // epilogue: out[j] = sum over 64 gibs of mean_g * lambda[g][j]
        float prt[16];
        #pragma unroll
        for (int j = 0; j < 16; j++)
            prt[j] = fmaf(acc0, L0[j], acc1 * L1[j]);

        #pragma unroll
        for (int off = 16; off >= 1; off >>= 1) {
            #pragma unroll
            for (int j = 0; j < 16; j++)
                prt[j] += __shfl_xor_sync(0xffffffffu, prt[j], off);
        }

        if (lane == 0) {
            float4* o = reinterpret_cast<float4*>(out + (size_t)q * 16);
            o[0] = make_float4(prt[0],  prt[1],  prt[2],  prt[3]);
            o[1] = make_float4(prt[4],  prt[5],  prt[6],  prt[7]);
            o[2] = make_float4(prt[8],  prt[9],  prt[10], prt[11]);
            o[3] = make_float4(prt[12], prt[13], prt[14], prt[15]);
        }
    }
}

extern "C" void kernel_launch(void* const* d_in, const int* in_sizes, int n_in,
                              void* d_out, int out_size)
{
    // metadata order: points, q_coords, support_idxs, mc_points (unused),
    //                 cy_params, cone_params, disk_params, ellip_params, lambdas
    const float* points       = (const float*)d_in[0];
    const float* q_coords     = (const float*)d_in[1];
    const int*   support_idxs = (const int*)  d_in[2];
    const float* cy_params    = (const float*)d_in[4];
    const float* cone_params  = (const float*)d_in[5];
    const float* disk_params  = (const float*)d_in[6];
    const float* ellip_params = (const float*)d_in[7];
    const float* lambdas      = (const float*)d_in[8];
    float* out = (float*)d_out;

    gib_kernel<<<GRID_BLOCKS, THREADS>>>(points, q_coords, support_idxs,
                                         cy_params, cone_params, disk_params,
                                         ellip_params, lambdas, out);
}

// round 2
// speedup vs baseline: 1.0986x; 1.0986x over previous
#include <cuda_runtime.h>
#include <cstdint>

// Problem constants: B=2, N=65536, M=8192, K=32
// TOTAL_GIBS=64 (16 cy, 16 cone, 16 disk, 16 ellip), NUM_OBSERVERS=16
#define EPSV 1e-8f
#define LOG2E_F 1.4426950408889634f

constexpr int Bc = 2;
constexpr int Nc = 65536;
constexpr int Mc = 8192;
constexpr int Kc = 32;
constexpr int NQ = Bc * Mc;          // 16384 queries
constexpr int WARPS_PER_BLOCK = 8;
constexpr int THREADS = WARPS_PER_BLOCK * 32;
constexpr int GRID_BLOCKS = NQ / WARPS_PER_BLOCK;   // 2048, one query per warp
constexpr int LPAD = 17;             // lambda row pad (17 coprime w/ 32 -> no bank conflicts)

__device__ __forceinline__ float ex2f(float x) {
    float r; asm("ex2.approx.ftz.f32 %0, %1;" : "=f"(r) : "f"(x)); return r;
}
__device__ __forceinline__ float sqrtaf(float x) {
    float r; asm("sqrt.approx.ftz.f32 %0, %1;" : "=f"(r) : "f"(x)); return r;
}

__global__ __launch_bounds__(THREADS, 4)
void gib_kernel(const float* __restrict__ points,
                const float* __restrict__ q_coords,
                const int*   __restrict__ support_idxs,
                const float* __restrict__ cy_p,
                const float* __restrict__ cone_p,
                const float* __restrict__ disk_p,
                const float* __restrict__ ellip_p,
                const float* __restrict__ lambdas,
                float* __restrict__ out)
{
    // per-warp point data: [warp][half][k] ; half 0 = data for lanes 0-15, half 1 = lanes 16-31
    __shared__ float4 sPts[WARPS_PER_BLOCK][2][Kc];
    // lambdas pre-scaled by 1/K, padded rows: sLam[g*LPAD + j]
    __shared__ float sLam[64 * LPAD];

    const int tid   = threadIdx.x;
    const int lane  = tid & 31;
    const int wslot = tid >> 5;
    const int q     = blockIdx.x * WARPS_PER_BLOCK + wslot;

    // cooperative lambda load (once per block)
    {
        const float invK = 1.f / (float)Kc;
        for (int i = tid; i < 64 * 16; i += THREADS) {
            int g = i >> 4, j = i & 15;
            sLam[g * LPAD + j] = lambdas[i] * invK;
        }
    }

    // ---- per-lane constants ----
    // quadratic gib (g0 = lane): t = p1*u + p2*rz + p3 ; arg0 = -t*t
    //   lane<16  -> cylinder:  u=r2,  p1=s0, p2=0,      p3=-s0*a^2
    //   lane>=16 -> cone:      u=s,   p1=s0, p2=-s0*a,  p3=0
    // linear gib (g1 = lane+32): a1 = q1*x1 + q2*x2 + q3*rz2
    //   lane<16  -> disk:  x1=r2, x2=0(junk slot stores 0), q3 on rz2
    //   lane>=16 -> ellip: x1=rx2, x2=ry2, q3 on rz2
    float p1, p2, p3, q1, q2, q3;
    if (lane < 16) {
        float a  = cy_p[lane * 2 + 0];
        float sg = cy_p[lane * 2 + 1];
        float s0 = sqrtf(LOG2E_F / (2.f * sg * sg + EPSV));
        p1 = s0; p2 = 0.f; p3 = -s0 * a * a;
        float d0 = disk_p[lane * 2 + 0];
        float d1 = disk_p[lane * 2 + 1];
        q1 = -LOG2E_F / (d0 * d0 + EPSV);
        q2 = 0.f;
        q3 = -LOG2E_F / (d1 * d1 + EPSV);
    } else {
        int j = lane - 16;
        float a  = cone_p[j * 2 + 0];
        float sg = cone_p[j * 2 + 1];
        float s0 = sqrtf(LOG2E_F / (2.f * sg * sg + EPSV));
        p1 = s0; p2 = -s0 * a; p3 = 0.f;
        float e0 = ellip_p[j * 3 + 0];
        float e1 = ellip_p[j * 3 + 1];
        float e2 = ellip_p[j * 3 + 2];
        q1 = -LOG2E_F / (e0 * e0 + EPSV);
        q2 = -LOG2E_F / (e1 * e1 + EPSV);
        q3 = -LOG2E_F / (e2 * e2 + EPSV);
    }

    // ---- gather phase: lane k handles support point k ----
    {
        const float* qc = q_coords + q * 3;
        float qx = __ldg(qc + 0);
        float qy = __ldg(qc + 1);
        float qz = __ldg(qc + 2);
        int   idx = __ldg(support_idxs + q * Kc + lane);
        int   b   = q >> 13;                      // q / Mc
        const float* p = points + ((size_t)(b * Nc + idx)) * 3;
        float rx = __ldg(p + 0) - qx;
        float ry = __ldg(p + 1) - qy;
        float rz = __ldg(p + 2) - qz;
        float rx2 = rx * rx;
        float ry2 = ry * ry;
        float r2  = rx2 + ry2;
        float s   = sqrtaf(r2 + EPSV);
        sPts[wslot][0][lane] = make_float4(r2, rz, r2, 0.f);     // low-lane view
        sPts[wslot][1][lane] = make_float4(s,  rz, rx2, ry2);    // high-lane view
    }
    __syncthreads();   // also covers sLam visibility

    // lane-dependent base: low lanes read half 0, high lanes half 1
    const float4* vbase = sPts[wslot][lane >> 4];

    float acc0 = 0.f, acc1 = 0.f;
    #pragma unroll
    for (int k = 0; k < Kc; k++) {
        float4 v  = vbase[k];                 // LDS.128, 2 broadcast groups
        float rz2 = v.y * v.y;
        float t   = fmaf(p1, v.x, fmaf(p2, v.y, p3));
        acc0 += ex2f(-t * t);
        float a1  = fmaf(q1, v.z, fmaf(q2, v.w, q3 * rz2));
        acc1 += ex2f(a1);
    }

    // ---- epilogue: out[q][j] = sum_g mean_g * lambda[g][j] ----
    const float* L0 = &sLam[lane * LPAD];
    const float* L1 = &sLam[(lane + 32) * LPAD];
    float prt[16];
    #pragma unroll
    for (int j = 0; j < 16; j++)
        prt[j] = fmaf(acc0, L0[j], acc1 * L1[j]);

    #pragma unroll
    for (int off = 16; off >= 1; off >>= 1) {
        #pragma unroll
        for (int j = 0; j < 16; j++)
            prt[j] += __shfl_xor_sync(0xffffffffu, prt[j], off);
    }

    if (lane == 0) {
        float4* o = reinterpret_cast<float4*>(out + (size_t)q * 16);
        o[0] = make_float4(prt[0],  prt[1],  prt[2],  prt[3]);
        o[1] = make_float4(prt[4],  prt[5],  prt[6],  prt[7]);
        o[2] = make_float4(prt[8],  prt[9],  prt[10], prt[11]);
        o[3] = make_float4(prt[12], prt[13], prt[14], prt[15]);
    }
}

extern "C" void kernel_launch(void* const* d_in, const int* in_sizes, int n_in,
                              void* d_out, int out_size)
{
    // metadata order: points, q_coords, support_idxs, mc_points (unused),
    //                 cy_params, cone_params, disk_params, ellip_params, lambdas
    const float* points       = (const float*)d_in[0];
    const float* q_coords     = (const float*)d_in[1];
    const int*   support_idxs = (const int*)  d_in[2];
    const float* cy_params    = (const float*)d_in[4];
    const float* cone_params  = (const float*)d_in[5];
    const float* disk_params  = (const float*)d_in[6];
    const float* ellip_params = (const float*)d_in[7];
    const float* lambdas      = (const float*)d_in[8];
    float* out = (float*)d_out;

    gib_kernel<<<GRID_BLOCKS, THREADS>>>(points, q_coords, support_idxs,
                                         cy_params, cone_params, disk_params,
                                         ellip_params, lambdas, out);
}

// round 3
// speedup vs baseline: 1.3384x; 1.2183x over previous
#include <cuda_runtime.h>
#include <cstdint>

// Problem constants: B=2, N=65536, M=8192, K=32
// TOTAL_GIBS=64 (16 cy, 16 cone, 16 disk, 16 ellip), NUM_OBSERVERS=16
#define EPSV 1e-8f
#define LOG2E_F 1.4426950408889634f

constexpr int Bc = 2;
constexpr int Nc = 65536;
constexpr int Mc = 8192;
constexpr int Kc = 32;
constexpr int NQ = Bc * Mc;                 // 16384 queries
constexpr int WARPS_PER_BLOCK = 8;
constexpr int THREADS = WARPS_PER_BLOCK * 32;
constexpr int Q_PER_WARP = 2;
constexpr int Q_PER_BLOCK = WARPS_PER_BLOCK * Q_PER_WARP;   // 16
constexpr int GRID_BLOCKS = NQ / Q_PER_BLOCK;               // 1024
constexpr int RPAD = 68;                    // padded row stride (words) for lamT/means

__device__ __forceinline__ float ex2f(float x) {
    float r; asm("ex2.approx.ftz.f32 %0, %1;" : "=f"(r) : "f"(x)); return r;
}
__device__ __forceinline__ float sqrtaf(float x) {
    float r; asm("sqrt.approx.ftz.f32 %0, %1;" : "=f"(r) : "f"(x)); return r;
}

__global__ __launch_bounds__(THREADS, 4)
void gib_kernel(const float* __restrict__ points,
                const float* __restrict__ q_coords,
                const int*   __restrict__ support_idxs,
                const float* __restrict__ cy_p,
                const float* __restrict__ cone_p,
                const float* __restrict__ disk_p,
                const float* __restrict__ ellip_p,
                const float* __restrict__ lambdas,
                float* __restrict__ out)
{
    // per-warp, per-query point data, 2 half-warp views: (u, rz, r2, rx2)
    // view 0 (lanes 0-15):  u = r2   ; view 1 (lanes 16-31): u = s = sqrt(r2+eps)
    __shared__ float4 sPts[WARPS_PER_BLOCK][Q_PER_WARP][2][Kc];   // 16 KB
    __shared__ float  lamT[16 * RPAD];       // lamT[j][g] = lambdas[g][j]/K
    __shared__ float  meanS[Q_PER_BLOCK * RPAD];  // meanS[qq][g]

    const int tid   = threadIdx.x;
    const int lane  = tid & 31;
    const int wslot = tid >> 5;
    const int qbase = blockIdx.x * Q_PER_BLOCK;
    const int qA    = qbase + wslot * 2;
    const int qB    = qA + 1;

    // ---- cooperative transposed lambda load (once per block) ----
    {
        const float invK = 1.f / (float)Kc;
        #pragma unroll
        for (int i = tid; i < 64 * 16; i += THREADS) {
            int g = i >> 4, j = i & 15;
            lamT[j * RPAD + g] = lambdas[i] * invK;
        }
    }

    // ---- per-lane gib constants (shared by both queries of this warp) ----
    // quadratic gib (g0=lane): t = p1*u + p2*rz + p3 ; contrib = 2^(-t*t)
    //   lane<16  cyl : u=r2, p1=s0, p2=0,     p3=-s0*a^2
    //   lane>=16 cone: u=s,  p1=s0, p2=-s0*a, p3=0
    // linear gib (g1=lane+32): a1 = q1p*rx2 + q2p*r2 + q3*rz2 ; contrib = 2^a1
    //   lane<16  disk : q1p=0,      q2p=-log2e/(d0^2+e), q3=-log2e/(d1^2+e)
    //   lane>=16 ellip: q1p=q1-q2,  q2p=q2 (per-axis reform via ry2 = r2-rx2)
    float p1, p2, p3, q1p, q2p, q3;
    if (lane < 16) {
        float a  = cy_p[lane * 2 + 0];
        float sg = cy_p[lane * 2 + 1];
        float s0 = sqrtf(LOG2E_F / (2.f * sg * sg + EPSV));
        p1 = s0; p2 = 0.f; p3 = -s0 * a * a;
        float d0 = disk_p[lane * 2 + 0];
        float d1 = disk_p[lane * 2 + 1];
        q1p = 0.f;
        q2p = -LOG2E_F / (d0 * d0 + EPSV);
        q3  = -LOG2E_F / (d1 * d1 + EPSV);
    } else {
        int j = lane - 16;
        float a  = cone_p[j * 2 + 0];
        float sg = cone_p[j * 2 + 1];
        float s0 = sqrtf(LOG2E_F / (2.f * sg * sg + EPSV));
        p1 = s0; p2 = -s0 * a; p3 = 0.f;
        float e0 = ellip_p[j * 3 + 0];
        float e1 = ellip_p[j * 3 + 1];
        float e2 = ellip_p[j * 3 + 2];
        float qx = -LOG2E_F / (e0 * e0 + EPSV);
        float qy = -LOG2E_F / (e1 * e1 + EPSV);
        q1p = qx - qy;
        q2p = qy;
        q3  = -LOG2E_F / (e2 * e2 + EPSV);
    }

    // ---- gather phase: lane k loads support point k for both queries ----
    {
        #pragma unroll
        for (int qq = 0; qq < Q_PER_WARP; qq++) {
            int q = qA + qq;
            const float* qc = q_coords + q * 3;
            float qx = __ldg(qc + 0);
            float qy = __ldg(qc + 1);
            float qz = __ldg(qc + 2);
            int   idx = __ldg(support_idxs + q * Kc + lane);
            int   b   = q >> 13;                 // q / Mc
            const float* p = points + ((size_t)(b * Nc + idx)) * 3;
            float rx = __ldg(p + 0) - qx;
            float ry = __ldg(p + 1) - qy;
            float rz = __ldg(p + 2) - qz;
            float rx2 = rx * rx;
            float ry2 = ry * ry;
            float r2  = rx2 + ry2;
            float s   = sqrtaf(r2 + EPSV);
            sPts[wslot][qq][0][lane] = make_float4(r2, rz, r2, rx2);
            sPts[wslot][qq][1][lane] = make_float4(s,  rz, r2, rx2);
        }
    }
    __syncwarp();

    const int half = lane >> 4;
    const float4* vA = sPts[wslot][0][half];
    const float4* vB = sPts[wslot][1][half];

    float acc0A = 0.f, acc1A = 0.f, acc0B = 0.f, acc1B = 0.f;
    #pragma unroll
    for (int k = 0; k < Kc; k++) {
        float4 a = vA[k];                    // LDS.128, broadcast x2 groups
        float4 b = vB[k];

        float tA   = fmaf(p1, a.x, fmaf(p2, a.y, p3));
        float tB   = fmaf(p1, b.x, fmaf(p2, b.y, p3));
        float rz2A = a.y * a.y;
        float rz2B = b.y * b.y;
        acc0A += ex2f(-tA * tA);
        acc0B += ex2f(-tB * tB);
        float a1A  = fmaf(q1p, a.w, fmaf(q2p, a.z, q3 * rz2A));
        float a1B  = fmaf(q1p, b.w, fmaf(q2p, b.z, q3 * rz2B));
        acc1A += ex2f(a1A);
        acc1B += ex2f(a1B);
    }

    // publish the 64 gib means for both queries
    {
        int qqA = wslot * 2, qqB = qqA + 1;
        meanS[qqA * RPAD + lane]      = acc0A;
        meanS[qqA * RPAD + lane + 32] = acc1A;
        meanS[qqB * RPAD + lane]      = acc0B;
        meanS[qqB * RPAD + lane + 32] = acc1B;
    }
    __syncthreads();

    // ---- block-cooperative epilogue: 16 queries x 16 observers, 1 per thread
    // out[qbase+qq][j] = sum_g meanS[qq][g] * lamT[j][g]
    {
        int qq = tid >> 4;
        int j  = tid & 15;
        const float4* mrow = reinterpret_cast<const float4*>(&meanS[qq * RPAD]);
        const float4* lrow = reinterpret_cast<const float4*>(&lamT[j * RPAD]);
        float acc = 0.f;
        #pragma unroll
        for (int g4 = 0; g4 < 16; g4++) {
            float4 m = mrow[g4];
            float4 l = lrow[g4];
            acc += m.x * l.x + m.y * l.y + m.z * l.z + m.w * l.w;
        }
        out[(size_t)(qbase + qq) * 16 + j] = acc;   // fully coalesced
    }
}

extern "C" void kernel_launch(void* const* d_in, const int* in_sizes, int n_in,
                              void* d_out, int out_size)
{
    // metadata order: points, q_coords, support_idxs, mc_points (unused),
    //                 cy_params, cone_params, disk_params, ellip_params, lambdas
    const float* points       = (const float*)d_in[0];
    const float* q_coords     = (const float*)d_in[1];
    const int*   support_idxs = (const int*)  d_in[2];
    const float* cy_params    = (const float*)d_in[4];
    const float* cone_params  = (const float*)d_in[5];
    const float* disk_params  = (const float*)d_in[6];
    const float* ellip_params = (const float*)d_in[7];
    const float* lambdas      = (const float*)d_in[8];
    float* out = (float*)d_out;

    gib_kernel<<<GRID_BLOCKS, THREADS>>>(points, q_coords, support_idxs,
                                         cy_params, cone_params, disk_params,
                                         ellip_params, lambdas, out);
}